// round 11
// baseline (speedup 1.0000x reference)
#include <cuda_runtime.h>
#include <cuda_fp16.h>

#define B   256
#define N   8192
#define C   32768
#define NSE 524288

#define TRANS_BLOCKS ((C / 128) * (B / 32))  // 256 * 8 = 2048
#define PREP_BLOCKS  (NSE / 4 / 256)         // 512
#define MAX_E 128                            // smem-staged edges per node (mean 64, max ~95)

// Scratch (device globals — no allocation allowed)
__device__ float4 g_pT4[(size_t)C * B / 8];           // exp(child_ll) transposed [C][B] fp16
__device__ __align__(16) uint2 g_edge[NSE + 2];       // {w as dup'd half2, col*512}
__device__ int    g_row_start[N + 1];

// K1 (fused): transpose+exp+fp16-pack for pT (128c x 32b tiles), AND edge prep.
__global__ __launch_bounds__(256) void prep_kernel(const float* __restrict__ ll,
                                                   const float* __restrict__ logw,
                                                   const int*   __restrict__ rows,
                                                   const int*   __restrict__ cols) {
    int t = threadIdx.x;
    if (blockIdx.x < TRANS_BLOCKS) {
        __shared__ float tile[32][129];
        int c0 = (blockIdx.x & (C / 128 - 1)) * 128;
        int b0 = (blockIdx.x >> 8) * 32;
        int row = t >> 3;
        int v   = t & 7;
        const float4* src = (const float4*)(ll + (size_t)(b0 + row) * C + c0);
#pragma unroll
        for (int j = 0; j < 4; j++) {
            float4 x = __ldg(&src[v + j * 8]);
            int col = (v + j * 8) * 4;
            tile[row][col + 0] = x.x;
            tile[row][col + 1] = x.y;
            tile[row][col + 2] = x.z;
            tile[row][col + 3] = x.w;
        }
        __syncthreads();
        int c_loc = t >> 1;
        int bofs  = (t & 1) * 16;
        uint4 outv[2];
        __half* hh = (__half*)outv;
#pragma unroll
        for (int j = 0; j < 16; j++)
            hh[j] = __float2half_rn(__expf(tile[bofs + j][c_loc]));
        __half* pT = (__half*)g_pT4;
        uint4* dst = (uint4*)&pT[(size_t)(c0 + c_loc) * B + b0 + bofs];
        dst[0] = outv[0];
        dst[1] = outv[1];
    } else {
        int e4 = (blockIdx.x - TRANS_BLOCKS) * 256 + t;
        int e  = e4 * 4;
        float4 lw = __ldg(&((const float4*)logw)[e4]);
        int4   cc = __ldg(&((const int4*)cols)[e4]);
        int4   rr = __ldg(&((const int4*)rows)[e4]);
        __half2 w0 = __float2half2_rn(__expf(lw.x));
        __half2 w1 = __float2half2_rn(__expf(lw.y));
        __half2 w2 = __float2half2_rn(__expf(lw.z));
        __half2 w3 = __float2half2_rn(__expf(lw.w));
        g_edge[e + 0] = make_uint2(*(unsigned*)&w0, (unsigned)cc.x * 512u);
        g_edge[e + 1] = make_uint2(*(unsigned*)&w1, (unsigned)cc.y * 512u);
        g_edge[e + 2] = make_uint2(*(unsigned*)&w2, (unsigned)cc.z * 512u);
        g_edge[e + 3] = make_uint2(*(unsigned*)&w3, (unsigned)cc.w * 512u);
        int rprev = (e == 0) ? -1 : __ldg(&rows[e - 1]);
        if (rr.x != rprev) g_row_start[rr.x] = e + 0;
        if (rr.y != rr.x)  g_row_start[rr.y] = e + 1;
        if (rr.z != rr.y)  g_row_start[rr.z] = e + 2;
        if (rr.w != rr.z)  g_row_start[rr.w] = e + 3;
        if (e == 0)        g_row_start[N]    = NSE;
    }
}

// fp16 chunk accumulate (4 batches): 2 HFMA2 + 1 HADD2 per edge
#define EDGEK(Ew, pv) {                                        \
    __half2 w2 = *(__half2*)&(Ew);                             \
    const __half2* ph = (const __half2*)&(pv);                 \
    hA = __hfma2(w2, ph[0], hA); hB = __hfma2(w2, ph[1], hB);  \
    hW = __hadd2(hW, w2); }

// fp32 scalar path, ed = uint2 edge record
#define EDGES(ed) {                                            \
    float we = __low2float(*(__half2*)&(ed).x);                \
    float2 pv = __ldg((const float2*)(pTb + (ed).y));          \
    const __half2* ph = (const __half2*)&pv;                   \
    float2 f;                                                  \
    f = __half22float2(ph[0]); a0 = fmaf(we, f.x, a0); a1 = fmaf(we, f.y, a1); \
    f = __half22float2(ph[1]); a2 = fmaf(we, f.x, a2); a3 = fmaf(we, f.y, a3); \
    wsum += we; }

// K2: 2 warps per node (128 batches each), 4 batches/lane.
// Edge list staged in smem; chunk-4 hot loop, low regs -> 6 blocks/SM.
__global__ __launch_bounds__(256, 6) void sum_kernel(float* __restrict__ out) {
    __shared__ float s_res[4][B];
    __shared__ __align__(16) uint2 slab[8][MAX_E];
    int warp = threadIdx.x >> 5;
    int lane = threadIdx.x & 31;
    int nloc = warp >> 1;                 // node within block
    int half = warp & 1;                  // 128-batch half
    int node = blockIdx.x * 4 + nloc;

    int e0 = g_row_start[node];
    int e1 = g_row_start[node + 1];
    int estart = e0 & ~1;                 // 16B-aligned global start
    int off    = e0 - estart;             // 0 or 1
    int total  = e1 - estart;
    int cpy    = total < MAX_E ? total : MAX_E;

    // Stage edge list into smem (fire-and-forget LDGSTS, 16B-aligned both sides)
    unsigned sbase = (unsigned)__cvta_generic_to_shared(&slab[warp][0]);
    const char* gsrc = (const char*)(g_edge + estart);
    int nchunks16 = (cpy + 1) >> 1;
    for (int i = lane; i < nchunks16; i += 32)
        asm volatile("cp.async.ca.shared.global [%0], [%1], 16;"
                     :: "r"(sbase + i * 16), "l"(gsrc + i * 16));
    asm volatile("cp.async.commit_group;");

    const char* pTb = (const char*)g_pT4 + half * 256 + lane * 8;
    const __half2 hz = __float2half2_rn(0.f);
    float a0 = 0.f, a1 = 0.f, a2 = 0.f, a3 = 0.f, wsum = 0.f;

    asm volatile("cp.async.wait_group 0;" ::: "memory");
    __syncwarp();

    const uint4* sl4 = (const uint4*)&slab[warp][0];   // 2 edges per uint4
    int i = off;
    if (i < cpy && (i & 1)) { uint2 ed = slab[warp][i]; EDGES(ed); i++; }
    for (; i + 4 <= cpy; i += 4) {
        // addresses from smem (broadcast LDS.128) -> 4 independent gathers
        uint4 E0 = sl4[(i >> 1) + 0];
        uint4 E1 = sl4[(i >> 1) + 1];
        float2 p0 = __ldg((const float2*)(pTb + E0.y));
        float2 p1 = __ldg((const float2*)(pTb + E0.w));
        float2 p2 = __ldg((const float2*)(pTb + E1.y));
        float2 p3 = __ldg((const float2*)(pTb + E1.w));
        __half2 hA = hz, hB = hz, hW = hz;
        EDGEK(E0.x, p0) EDGEK(E0.z, p1) EDGEK(E1.x, p2) EDGEK(E1.z, p3)
        float2 f;
        f = __half22float2(hA); a0 += f.x; a1 += f.y;
        f = __half22float2(hB); a2 += f.x; a3 += f.y;
        wsum += __low2float(hW);
    }
    for (; i < cpy; i++) { uint2 ed = slab[warp][i]; EDGES(ed); }
    // overflow beyond MAX_E (statistically never; correctness guard)
    for (int e = estart + cpy; e < e1; e++) { uint2 ed = __ldg(&g_edge[e]); EDGES(ed); }

    float lz = __logf(wsum);
    float4 r = make_float4(__logf(a0) - lz, __logf(a1) - lz,
                           __logf(a2) - lz, __logf(a3) - lz);
    *(float4*)&s_res[nloc][half * 128 + lane * 4] = r;
    __syncthreads();

    // Transposed write-out: thread b writes 4 consecutive nodes (16B)
    int bb = threadIdx.x;   // 0..255 == B
    float4 v = make_float4(s_res[0][bb], s_res[1][bb], s_res[2][bb], s_res[3][bb]);
    *(float4*)(out + (size_t)bb * N + (size_t)blockIdx.x * 4) = v;
}

extern "C" void kernel_launch(void* const* d_in, const int* in_sizes, int n_in,
                              void* d_out, int out_size) {
    const float* child_ll = (const float*)d_in[0];  // [B, C]
    const float* log_w    = (const float*)d_in[1];  // [NSE]
    const int*   rows     = (const int*)d_in[2];    // [NSE], sorted
    const int*   cols     = (const int*)d_in[3];    // [NSE]
    float*       out      = (float*)d_out;          // [B, N]

    prep_kernel<<<TRANS_BLOCKS + PREP_BLOCKS, 256>>>(child_ll, log_w, rows, cols);
    sum_kernel<<<N / 4, 256>>>(out);
}

// round 12
// speedup vs baseline: 1.0629x; 1.0629x over previous
#include <cuda_runtime.h>
#include <cuda_fp16.h>

#define B   256
#define N   8192
#define C   32768
#define NSE 524288

#define TRANS_BLOCKS ((C / 128) * (B / 32))  // 256 * 8 = 2048
#define PREP_BLOCKS  (NSE / 4 / 256)         // 512
#define MAX_E 128                            // smem-staged edges per node (mean 64, max ~95)

// Scratch (device globals — no allocation allowed)
__device__ float4 g_pT4[(size_t)C * B / 8];           // exp(child_ll) transposed [C][B] fp16
__device__ __align__(16) uint2 g_edge[NSE + 2];       // {w as dup'd half2, col*512}
__device__ int    g_row_start[N + 1];

// K1 (fused): transpose+exp+fp16-pack for pT (128c x 32b tiles), AND edge prep.
__global__ __launch_bounds__(256) void prep_kernel(const float* __restrict__ ll,
                                                   const float* __restrict__ logw,
                                                   const int*   __restrict__ rows,
                                                   const int*   __restrict__ cols) {
    int t = threadIdx.x;
    if (blockIdx.x < TRANS_BLOCKS) {
        __shared__ float tile[32][129];
        int c0 = (blockIdx.x & (C / 128 - 1)) * 128;
        int b0 = (blockIdx.x >> 8) * 32;
        int row = t >> 3;
        int v   = t & 7;
        const float4* src = (const float4*)(ll + (size_t)(b0 + row) * C + c0);
#pragma unroll
        for (int j = 0; j < 4; j++) {
            float4 x = __ldg(&src[v + j * 8]);
            int col = (v + j * 8) * 4;
            tile[row][col + 0] = x.x;
            tile[row][col + 1] = x.y;
            tile[row][col + 2] = x.z;
            tile[row][col + 3] = x.w;
        }
        __syncthreads();
        int c_loc = t >> 1;
        int bofs  = (t & 1) * 16;
        uint4 outv[2];
        __half* hh = (__half*)outv;
#pragma unroll
        for (int j = 0; j < 16; j++)
            hh[j] = __float2half_rn(__expf(tile[bofs + j][c_loc]));
        __half* pT = (__half*)g_pT4;
        uint4* dst = (uint4*)&pT[(size_t)(c0 + c_loc) * B + b0 + bofs];
        dst[0] = outv[0];
        dst[1] = outv[1];
    } else {
        int e4 = (blockIdx.x - TRANS_BLOCKS) * 256 + t;
        int e  = e4 * 4;
        float4 lw = __ldg(&((const float4*)logw)[e4]);
        int4   cc = __ldg(&((const int4*)cols)[e4]);
        int4   rr = __ldg(&((const int4*)rows)[e4]);
        __half2 w0 = __float2half2_rn(__expf(lw.x));
        __half2 w1 = __float2half2_rn(__expf(lw.y));
        __half2 w2 = __float2half2_rn(__expf(lw.z));
        __half2 w3 = __float2half2_rn(__expf(lw.w));
        g_edge[e + 0] = make_uint2(*(unsigned*)&w0, (unsigned)cc.x * 512u);
        g_edge[e + 1] = make_uint2(*(unsigned*)&w1, (unsigned)cc.y * 512u);
        g_edge[e + 2] = make_uint2(*(unsigned*)&w2, (unsigned)cc.z * 512u);
        g_edge[e + 3] = make_uint2(*(unsigned*)&w3, (unsigned)cc.w * 512u);
        int rprev = (e == 0) ? -1 : __ldg(&rows[e - 1]);
        if (rr.x != rprev) g_row_start[rr.x] = e + 0;
        if (rr.y != rr.x)  g_row_start[rr.y] = e + 1;
        if (rr.z != rr.y)  g_row_start[rr.z] = e + 2;
        if (rr.w != rr.z)  g_row_start[rr.w] = e + 3;
        if (e == 0)        g_row_start[N]    = NSE;
    }
}

// fp16 chunk accumulate (8 batches): 4 HFMA2 + 1 HADD2 per edge
#define EDGEK(Ew, pv) {                                        \
    __half2 w2 = *(__half2*)&(Ew);                             \
    const __half2* ph = (const __half2*)&(pv);                 \
    hA = __hfma2(w2, ph[0], hA); hB = __hfma2(w2, ph[1], hB);  \
    hC = __hfma2(w2, ph[2], hC); hD = __hfma2(w2, ph[3], hD);  \
    hW = __hadd2(hW, w2); }

// fp32 scalar path, ed = uint2 edge record (8 batches)
#define EDGES(ed) {                                            \
    float we = __low2float(*(__half2*)&(ed).x);                \
    float4 pv = __ldg((const float4*)(pTb + (ed).y));          \
    const __half2* ph = (const __half2*)&pv;                   \
    float2 f;                                                  \
    f = __half22float2(ph[0]); a0 = fmaf(we, f.x, a0); a1 = fmaf(we, f.y, a1); \
    f = __half22float2(ph[1]); a2 = fmaf(we, f.x, a2); a3 = fmaf(we, f.y, a3); \
    f = __half22float2(ph[2]); a4 = fmaf(we, f.x, a4); a5 = fmaf(we, f.y, a5); \
    f = __half22float2(ph[3]); a6 = fmaf(we, f.x, a6); a7 = fmaf(we, f.y, a7); \
    wsum += we; }

// K2: 1 warp per node (all 256 batches, 8/lane via float4), smem-staged edges,
// chunk-4 hot loop: 2 LDS.128 + 4 independent LDG.128 per 4 edges.
__global__ __launch_bounds__(256, 5) void sum_kernel(float* __restrict__ out) {
    __shared__ float s_res[8][B];
    __shared__ __align__(16) uint2 slab[8][MAX_E];
    int warp = threadIdx.x >> 5;
    int lane = threadIdx.x & 31;
    int node = blockIdx.x * 8 + warp;

    int e0 = g_row_start[node];
    int e1 = g_row_start[node + 1];
    int estart = e0 & ~1;                 // 16B-aligned global start
    int off    = e0 - estart;             // 0 or 1
    int total  = e1 - estart;
    int cpy    = total < MAX_E ? total : MAX_E;

    // Stage edge list into smem (fire-and-forget LDGSTS, 16B-aligned both sides)
    unsigned sbase = (unsigned)__cvta_generic_to_shared(&slab[warp][0]);
    const char* gsrc = (const char*)(g_edge + estart);
    int nchunks16 = (cpy + 1) >> 1;
    for (int i = lane; i < nchunks16; i += 32)
        asm volatile("cp.async.ca.shared.global [%0], [%1], 16;"
                     :: "r"(sbase + i * 16), "l"(gsrc + i * 16));
    asm volatile("cp.async.commit_group;");

    const char* pTb = (const char*)g_pT4 + lane * 16;
    const __half2 hz = __float2half2_rn(0.f);
    float a0 = 0.f, a1 = 0.f, a2 = 0.f, a3 = 0.f;
    float a4 = 0.f, a5 = 0.f, a6 = 0.f, a7 = 0.f, wsum = 0.f;

    asm volatile("cp.async.wait_group 0;" ::: "memory");
    __syncwarp();

    const uint4* sl4 = (const uint4*)&slab[warp][0];   // 2 edges per uint4
    int i = off;
    if (i < cpy && (i & 1)) { uint2 ed = slab[warp][i]; EDGES(ed); i++; }
    for (; i + 4 <= cpy; i += 4) {
        // addresses from smem (broadcast LDS.128) -> 4 independent 512B gathers
        uint4 E0 = sl4[(i >> 1) + 0];
        uint4 E1 = sl4[(i >> 1) + 1];
        float4 p0 = __ldg((const float4*)(pTb + E0.y));
        float4 p1 = __ldg((const float4*)(pTb + E0.w));
        float4 p2 = __ldg((const float4*)(pTb + E1.y));
        float4 p3 = __ldg((const float4*)(pTb + E1.w));
        __half2 hA = hz, hB = hz, hC = hz, hD = hz, hW = hz;
        EDGEK(E0.x, p0) EDGEK(E0.z, p1) EDGEK(E1.x, p2) EDGEK(E1.z, p3)
        float2 f;
        f = __half22float2(hA); a0 += f.x; a1 += f.y;
        f = __half22float2(hB); a2 += f.x; a3 += f.y;
        f = __half22float2(hC); a4 += f.x; a5 += f.y;
        f = __half22float2(hD); a6 += f.x; a7 += f.y;
        wsum += __low2float(hW);
    }
    for (; i < cpy; i++) { uint2 ed = slab[warp][i]; EDGES(ed); }
    // overflow beyond MAX_E (statistically never; correctness guard)
    for (int e = estart + cpy; e < e1; e++) { uint2 ed = __ldg(&g_edge[e]); EDGES(ed); }

    float lz = __logf(wsum);
    float4 r0 = make_float4(__logf(a0) - lz, __logf(a1) - lz,
                            __logf(a2) - lz, __logf(a3) - lz);
    float4 r1 = make_float4(__logf(a4) - lz, __logf(a5) - lz,
                            __logf(a6) - lz, __logf(a7) - lz);
    float4* sr = (float4*)&s_res[warp][lane * 8];
    sr[0] = r0;
    sr[1] = r1;
    __syncthreads();

    // Transposed write-out: thread b writes 8 consecutive nodes (32B)
    int bb = threadIdx.x;   // 0..255 == B
    float4 v0 = make_float4(s_res[0][bb], s_res[1][bb], s_res[2][bb], s_res[3][bb]);
    float4 v1 = make_float4(s_res[4][bb], s_res[5][bb], s_res[6][bb], s_res[7][bb]);
    float4* o = (float4*)(out + (size_t)bb * N + (size_t)blockIdx.x * 8);
    o[0] = v0;
    o[1] = v1;
}

extern "C" void kernel_launch(void* const* d_in, const int* in_sizes, int n_in,
                              void* d_out, int out_size) {
    const float* child_ll = (const float*)d_in[0];  // [B, C]
    const float* log_w    = (const float*)d_in[1];  // [NSE]
    const int*   rows     = (const int*)d_in[2];    // [NSE], sorted
    const int*   cols     = (const int*)d_in[3];    // [NSE]
    float*       out      = (float*)d_out;          // [B, N]

    prep_kernel<<<TRANS_BLOCKS + PREP_BLOCKS, 256>>>(child_ll, log_w, rows, cols);
    sum_kernel<<<N / 8, 256>>>(out);
}

// round 13
// speedup vs baseline: 1.1074x; 1.0419x over previous
#include <cuda_runtime.h>
#include <cuda_fp16.h>

#define B   256
#define N   8192
#define C   32768
#define NSE 524288

#define TRANS_BLOCKS ((C / 128) * (B / 32))  // 256 * 8 = 2048
#define PREP_BLOCKS  (NSE / 4 / 256)         // 512
#define MAX_E 128                            // smem-staged edges per node (mean 64, max ~95)

// Scratch (device globals — no allocation allowed)
__device__ float4 g_pT4[(size_t)C * B / 8];           // exp(child_ll) transposed [C][B] fp16
__device__ __align__(16) uint2 g_edge[NSE + 2];       // {w as dup'd half2, col*512}
__device__ int    g_row_start[N + 1];

// K1 (fused): transpose+exp+fp16-pack for pT (128c x 32b tiles), AND edge prep.
__global__ __launch_bounds__(256) void prep_kernel(const float* __restrict__ ll,
                                                   const float* __restrict__ logw,
                                                   const int*   __restrict__ rows,
                                                   const int*   __restrict__ cols) {
    int t = threadIdx.x;
    if (blockIdx.x < TRANS_BLOCKS) {
        __shared__ float tile[32][129];
        int c0 = (blockIdx.x & (C / 128 - 1)) * 128;
        int b0 = (blockIdx.x >> 8) * 32;
        int row = t >> 3;
        int v   = t & 7;
        const float4* src = (const float4*)(ll + (size_t)(b0 + row) * C + c0);
#pragma unroll
        for (int j = 0; j < 4; j++) {
            float4 x = __ldg(&src[v + j * 8]);
            int col = (v + j * 8) * 4;
            tile[row][col + 0] = x.x;
            tile[row][col + 1] = x.y;
            tile[row][col + 2] = x.z;
            tile[row][col + 3] = x.w;
        }
        __syncthreads();
        int c_loc = t >> 1;
        int bofs  = (t & 1) * 16;
        uint4 outv[2];
        __half* hh = (__half*)outv;
#pragma unroll
        for (int j = 0; j < 16; j++)
            hh[j] = __float2half_rn(__expf(tile[bofs + j][c_loc]));
        __half* pT = (__half*)g_pT4;
        uint4* dst = (uint4*)&pT[(size_t)(c0 + c_loc) * B + b0 + bofs];
        dst[0] = outv[0];
        dst[1] = outv[1];
    } else {
        int e4 = (blockIdx.x - TRANS_BLOCKS) * 256 + t;
        int e  = e4 * 4;
        float4 lw = __ldg(&((const float4*)logw)[e4]);
        int4   cc = __ldg(&((const int4*)cols)[e4]);
        int4   rr = __ldg(&((const int4*)rows)[e4]);
        __half2 w0 = __float2half2_rn(__expf(lw.x));
        __half2 w1 = __float2half2_rn(__expf(lw.y));
        __half2 w2 = __float2half2_rn(__expf(lw.z));
        __half2 w3 = __float2half2_rn(__expf(lw.w));
        g_edge[e + 0] = make_uint2(*(unsigned*)&w0, (unsigned)cc.x * 512u);
        g_edge[e + 1] = make_uint2(*(unsigned*)&w1, (unsigned)cc.y * 512u);
        g_edge[e + 2] = make_uint2(*(unsigned*)&w2, (unsigned)cc.z * 512u);
        g_edge[e + 3] = make_uint2(*(unsigned*)&w3, (unsigned)cc.w * 512u);
        int rprev = (e == 0) ? -1 : __ldg(&rows[e - 1]);
        if (rr.x != rprev) g_row_start[rr.x] = e + 0;
        if (rr.y != rr.x)  g_row_start[rr.y] = e + 1;
        if (rr.z != rr.y)  g_row_start[rr.z] = e + 2;
        if (rr.w != rr.z)  g_row_start[rr.w] = e + 3;
        if (e == 0)        g_row_start[N]    = NSE;
    }
}

// fp16 chunk accumulate (4 batches): 2 HFMA2 + 1 HADD2 per edge
#define EDGEK(Ew, pv) {                                        \
    __half2 w2 = *(__half2*)&(Ew);                             \
    const __half2* ph = (const __half2*)&(pv);                 \
    hA = __hfma2(w2, ph[0], hA); hB = __hfma2(w2, ph[1], hB);  \
    hW = __hadd2(hW, w2); }

// fp32 scalar path, ed = uint2 edge record
#define EDGES(ed) {                                            \
    float we = __low2float(*(__half2*)&(ed).x);                \
    float2 pv = __ldg((const float2*)(pTb + (ed).y));          \
    const __half2* ph = (const __half2*)&pv;                   \
    float2 f;                                                  \
    f = __half22float2(ph[0]); a0 = fmaf(we, f.x, a0); a1 = fmaf(we, f.y, a1); \
    f = __half22float2(ph[1]); a2 = fmaf(we, f.x, a2); a3 = fmaf(we, f.y, a3); \
    wsum += we; }

// K2: 2 warps per node (128 batches each, 4/lane), shared per-node smem slab
// (staged once by 64 lanes), chunk-8 hot loop (R9 winner), 5 blocks/SM.
__global__ __launch_bounds__(256, 5) void sum_kernel(float* __restrict__ out) {
    __shared__ float s_res[4][B];
    __shared__ __align__(16) uint2 slab[4][MAX_E];
    int warp = threadIdx.x >> 5;
    int lane = threadIdx.x & 31;
    int nloc = warp >> 1;                 // node within block (0..3)
    int half = warp & 1;                  // 128-batch half
    int node = blockIdx.x * 4 + nloc;

    int e0 = g_row_start[node];
    int e1 = g_row_start[node + 1];
    int estart = e0 & ~1;                 // 16B-aligned global start
    int off    = e0 - estart;             // 0 or 1
    int total  = e1 - estart;
    int cpy    = total < MAX_E ? total : MAX_E;

    // Stage this node's edges ONCE, using both warps (64 lanes, <=64 chunks)
    {
        int lane64 = half * 32 + lane;
        int nchunks16 = (cpy + 1) >> 1;
        if (lane64 < nchunks16) {
            unsigned sdst = (unsigned)__cvta_generic_to_shared(&slab[nloc][0]) + lane64 * 16;
            const char* gsrc = (const char*)(g_edge + estart) + lane64 * 16;
            asm volatile("cp.async.ca.shared.global [%0], [%1], 16;"
                         :: "r"(sdst), "l"(gsrc));
        }
        asm volatile("cp.async.commit_group;");
        asm volatile("cp.async.wait_group 0;" ::: "memory");
    }
    __syncthreads();   // slab visible to both warps of each node

    const char* pTb = (const char*)g_pT4 + half * 256 + lane * 8;
    const __half2 hz = __float2half2_rn(0.f);
    float a0 = 0.f, a1 = 0.f, a2 = 0.f, a3 = 0.f, wsum = 0.f;

    const uint4* sl4 = (const uint4*)&slab[nloc][0];   // 2 edges per uint4
    int i = off;
    if (i < cpy && (i & 1)) { uint2 ed = slab[nloc][i]; EDGES(ed); i++; }
    for (; i + 8 <= cpy; i += 8) {
        // addresses from smem (broadcast LDS.128) -> 8 independent gathers
        uint4 E0 = sl4[(i >> 1) + 0];
        uint4 E1 = sl4[(i >> 1) + 1];
        uint4 E2 = sl4[(i >> 1) + 2];
        uint4 E3 = sl4[(i >> 1) + 3];
        float2 p0 = __ldg((const float2*)(pTb + E0.y));
        float2 p1 = __ldg((const float2*)(pTb + E0.w));
        float2 p2 = __ldg((const float2*)(pTb + E1.y));
        float2 p3 = __ldg((const float2*)(pTb + E1.w));
        float2 p4 = __ldg((const float2*)(pTb + E2.y));
        float2 p5 = __ldg((const float2*)(pTb + E2.w));
        float2 p6 = __ldg((const float2*)(pTb + E3.y));
        float2 p7 = __ldg((const float2*)(pTb + E3.w));
        __half2 hA = hz, hB = hz, hW = hz;
        EDGEK(E0.x, p0) EDGEK(E0.z, p1) EDGEK(E1.x, p2) EDGEK(E1.z, p3)
        EDGEK(E2.x, p4) EDGEK(E2.z, p5) EDGEK(E3.x, p6) EDGEK(E3.z, p7)
        float2 f;
        f = __half22float2(hA); a0 += f.x; a1 += f.y;
        f = __half22float2(hB); a2 += f.x; a3 += f.y;
        wsum += __low2float(hW);
    }
    for (; i < cpy; i++) { uint2 ed = slab[nloc][i]; EDGES(ed); }
    // overflow beyond MAX_E (statistically never; correctness guard)
    for (int e = estart + cpy; e < e1; e++) { uint2 ed = __ldg(&g_edge[e]); EDGES(ed); }

    float lz = __logf(wsum);
    float4 r = make_float4(__logf(a0) - lz, __logf(a1) - lz,
                           __logf(a2) - lz, __logf(a3) - lz);
    *(float4*)&s_res[nloc][half * 128 + lane * 4] = r;
    __syncthreads();

    // Transposed write-out: thread b writes 4 consecutive nodes (16B)
    int bb = threadIdx.x;   // 0..255 == B
    float4 v = make_float4(s_res[0][bb], s_res[1][bb], s_res[2][bb], s_res[3][bb]);
    *(float4*)(out + (size_t)bb * N + (size_t)blockIdx.x * 4) = v;
}

extern "C" void kernel_launch(void* const* d_in, const int* in_sizes, int n_in,
                              void* d_out, int out_size) {
    const float* child_ll = (const float*)d_in[0];  // [B, C]
    const float* log_w    = (const float*)d_in[1];  // [NSE]
    const int*   rows     = (const int*)d_in[2];    // [NSE], sorted
    const int*   cols     = (const int*)d_in[3];    // [NSE]
    float*       out      = (float*)d_out;          // [B, N]

    prep_kernel<<<TRANS_BLOCKS + PREP_BLOCKS, 256>>>(child_ll, log_w, rows, cols);
    sum_kernel<<<N / 4, 256>>>(out);
}